// round 15
// baseline (speedup 1.0000x reference)
#include <cuda_runtime.h>
#include <cuda_bf16.h>

// Problem shapes (fixed by reference setup_inputs)
#define B    4
#define CIN  512
#define OUT  256
#define NN   4096

// Scratch (no cudaMalloc allowed); fully overwritten every run
__device__ float g_X[B * CIN];   // X[b,c] = sum_n x[b,c,n]

// ---- Blackwell 256-bit global memory ops (sm_100+) ----
__device__ __forceinline__ float ld256_sum(const float* p) {
    float a, b, c, d, e, f, g, h;
    asm volatile("ld.global.nc.v8.f32 {%0,%1,%2,%3,%4,%5,%6,%7}, [%8];"
                 : "=f"(a), "=f"(b), "=f"(c), "=f"(d),
                   "=f"(e), "=f"(f), "=f"(g), "=f"(h)
                 : "l"(p));
    return ((a + b) + (c + d)) + ((e + f) + (g + h));
}
__device__ __forceinline__ void st256_splat(float* p, float v) {
    asm volatile("st.global.v8.f32 [%0], {%1,%1,%1,%1,%1,%1,%1,%1};"
                 :: "l"(p), "f"(v) : "memory");
}

// ---------------------------------------------------------------------------
// Kernel 1: reduce x over N. One block per (b,c) row (16 KB each).
// 256 threads x 2 x 256-bit loads (same proven shape, half the LDG count).
// ---------------------------------------------------------------------------
__global__ __launch_bounds__(256) void k_rowsum(const float* __restrict__ x) {
    const int row = blockIdx.x;                 // 0 .. B*CIN-1
    const float* __restrict__ base = x + (size_t)row * NN;
    const int t = threadIdx.x;

    // two independent 32-byte loads per thread (row = 512 v8-chunks)
    float s = ld256_sum(base + (size_t)t * 8)
            + ld256_sum(base + (size_t)(t + 256) * 8);

    #pragma unroll
    for (int off = 16; off > 0; off >>= 1)
        s += __shfl_down_sync(0xffffffffu, s, off);

    __shared__ float sm[8];
    if ((t & 31) == 0) sm[t >> 5] = s;
    __syncthreads();
    if (t < 8) {
        float u = sm[t];
        #pragma unroll
        for (int off = 4; off > 0; off >>= 1)
            u += __shfl_down_sync(0xffu, u, off);
        if (t == 0) g_X[row] = u;
    }

    // Allow the dependent kernel to start mounting / running its prologue.
    cudaTriggerProgrammaticLaunchCompletion();
}

// ---------------------------------------------------------------------------
// Kernel 2: 1024 blocks x 256 threads, one output row per block.
// Every warp redundantly computes the row's 512-dot (L1/L2-hot) -> no
// __syncthreads, no shared; stores via 2 x 256-bit STG per lane.
// PDL: W1 prologue runs before cudaGridDependencySynchronize().
// ---------------------------------------------------------------------------
__global__ __launch_bounds__(256) void k_out(const float* __restrict__ W1,
                                             float* __restrict__ out) {
    const int bo   = blockIdx.x;       // 0 .. 1023
    const int b    = bo >> 8;          // OUT = 256
    const int o    = bo & 255;
    const int warp = threadIdx.x >> 5; // 0..7
    const int lane = threadIdx.x & 31;

    // ---- prologue (independent of k_rowsum): load W1 row ----
    const float4* __restrict__ wr =
        reinterpret_cast<const float4*>(W1) + (size_t)o * (CIN / 4);
    float4 a0 = wr[lane];       float4 a1 = wr[lane + 32];
    float4 a2 = wr[lane + 64];  float4 a3 = wr[lane + 96];

    // ---- wait for k_rowsum's memory to be visible ----
    cudaGridDependencySynchronize();

    const float4* __restrict__ xr =
        reinterpret_cast<const float4*>(g_X) + (size_t)b * (CIN / 4);
    float4 b0 = xr[lane];       float4 b1 = xr[lane + 32];
    float4 b2 = xr[lane + 64];  float4 b3 = xr[lane + 96];

    float s0 = fmaf(a0.x, b0.x, fmaf(a0.y, b0.y, fmaf(a0.z, b0.z, a0.w * b0.w)));
    float s1 = fmaf(a1.x, b1.x, fmaf(a1.y, b1.y, fmaf(a1.z, b1.z, a1.w * b1.w)));
    float s2 = fmaf(a2.x, b2.x, fmaf(a2.y, b2.y, fmaf(a2.z, b2.z, a2.w * b2.w)));
    float s3 = fmaf(a3.x, b3.x, fmaf(a3.y, b3.y, fmaf(a3.z, b3.z, a3.w * b3.w)));
    float s  = (s0 + s1) + (s2 + s3);

    #pragma unroll
    for (int off = 16; off > 0; off >>= 1)     // butterfly: all lanes get sum
        s += __shfl_xor_sync(0xffffffffu, s, off);

    const float e = (s > 0.f) ? s : expm1f(s);     // elu, alpha=1

    // warp owns floats [warp*512, warp*512+512) of this 4096-float row:
    // 32 lanes x 2 x 8-float (32 B) stores = 512 floats.
    float* __restrict__ q = out + (size_t)bo * NN + warp * 512;
    st256_splat(q + lane * 8,       e);
    st256_splat(q + lane * 8 + 256, e);
}

extern "C" void kernel_launch(void* const* d_in, const int* in_sizes, int n_in,
                              void* d_out, int out_size) {
    const float* x  = (const float*)d_in[0];   // [B, CIN, 1, NN]
    const float* W1 = (const float*)d_in[1];   // [OUT, CIN]
    // d_in[2] = w2, d_in[3] = bias_mat: unused (softmax over size-1 axis == 1)
    float* out = (float*)d_out;                // [B, OUT, 1, NN]

    k_rowsum<<<B * CIN, 256>>>(x);

    // Secondary launch with Programmatic Stream Serialization (PDL overlap).
    cudaLaunchConfig_t cfg = {};
    cfg.gridDim  = dim3(B * OUT, 1, 1);
    cfg.blockDim = dim3(256, 1, 1);
    cfg.dynamicSmemBytes = 0;
    cfg.stream = 0;
    cudaLaunchAttribute attr[1];
    attr[0].id = cudaLaunchAttributeProgrammaticStreamSerialization;
    attr[0].val.programmaticStreamSerializationAllowed = 1;
    cfg.attrs = attr;
    cfg.numAttrs = 1;
    cudaLaunchKernelEx(&cfg, k_out, W1, out);
}

// round 16
// speedup vs baseline: 1.2149x; 1.2149x over previous
#include <cuda_runtime.h>
#include <cuda_bf16.h>

// Problem shapes (fixed by reference setup_inputs)
#define B    4
#define CIN  512
#define OUT  256
#define NN   4096

// Scratch (no cudaMalloc allowed); fully overwritten every run
__device__ float g_X[B * CIN];   // X[b,c] = sum_n x[b,c,n]

// ---------------------------------------------------------------------------
// Kernel 1: reduce x over N. One block per (b,c) row (16 KB each).
// 256 threads x 4 front-batched float4. Triggers PDL completion at the end.
// (Best measured shape across 15 rounds.)
// ---------------------------------------------------------------------------
__global__ __launch_bounds__(256) void k_rowsum(const float* __restrict__ x) {
    const int row = blockIdx.x;                 // 0 .. B*CIN-1
    const float4* __restrict__ p =
        reinterpret_cast<const float4*>(x + (size_t)row * NN);
    const int t = threadIdx.x;

    float4 v0 = p[t];
    float4 v1 = p[t + 256];
    float4 v2 = p[t + 512];
    float4 v3 = p[t + 768];

    float s0 = (v0.x + v0.y) + (v0.z + v0.w);
    float s1 = (v1.x + v1.y) + (v1.z + v1.w);
    float s2 = (v2.x + v2.y) + (v2.z + v2.w);
    float s3 = (v3.x + v3.y) + (v3.z + v3.w);
    float s  = (s0 + s1) + (s2 + s3);

    #pragma unroll
    for (int off = 16; off > 0; off >>= 1)
        s += __shfl_down_sync(0xffffffffu, s, off);

    __shared__ float sm[8];
    if ((t & 31) == 0) sm[t >> 5] = s;
    __syncthreads();
    if (t < 8) {
        float u = sm[t];
        #pragma unroll
        for (int off = 4; off > 0; off >>= 1)
            u += __shfl_down_sync(0xffu, u, off);
        if (t == 0) g_X[row] = u;
    }

    // Allow the dependent kernel to start mounting / running its prologue.
    cudaTriggerProgrammaticLaunchCompletion();
}

// ---------------------------------------------------------------------------
// Kernel 2: 1024 blocks x 256 threads, one output row per block.
// Every warp REDUNDANTLY computes the row's 512-dot (L1/L2-hot, trivial cost)
// -> no __syncthreads, no shared memory, 8 fully independent store streams.
// PDL: W1 prologue runs before cudaGridDependencySynchronize().
// ---------------------------------------------------------------------------
__global__ __launch_bounds__(256) void k_out(const float* __restrict__ W1,
                                             float* __restrict__ out) {
    const int bo   = blockIdx.x;       // 0 .. 1023
    const int b    = bo >> 8;          // OUT = 256
    const int o    = bo & 255;
    const int warp = threadIdx.x >> 5; // 0..7
    const int lane = threadIdx.x & 31;

    // ---- prologue (independent of k_rowsum): load W1 row ----
    const float4* __restrict__ wr =
        reinterpret_cast<const float4*>(W1) + (size_t)o * (CIN / 4);
    float4 a0 = wr[lane];       float4 a1 = wr[lane + 32];
    float4 a2 = wr[lane + 64];  float4 a3 = wr[lane + 96];

    // ---- wait for k_rowsum's memory to be visible ----
    cudaGridDependencySynchronize();

    const float4* __restrict__ xr =
        reinterpret_cast<const float4*>(g_X) + (size_t)b * (CIN / 4);
    float4 b0 = xr[lane];       float4 b1 = xr[lane + 32];
    float4 b2 = xr[lane + 64];  float4 b3 = xr[lane + 96];

    float s0 = fmaf(a0.x, b0.x, fmaf(a0.y, b0.y, fmaf(a0.z, b0.z, a0.w * b0.w)));
    float s1 = fmaf(a1.x, b1.x, fmaf(a1.y, b1.y, fmaf(a1.z, b1.z, a1.w * b1.w)));
    float s2 = fmaf(a2.x, b2.x, fmaf(a2.y, b2.y, fmaf(a2.z, b2.z, a2.w * b2.w)));
    float s3 = fmaf(a3.x, b3.x, fmaf(a3.y, b3.y, fmaf(a3.z, b3.z, a3.w * b3.w)));
    float s  = (s0 + s1) + (s2 + s3);

    #pragma unroll
    for (int off = 16; off > 0; off >>= 1)     // butterfly: all lanes get sum
        s += __shfl_xor_sync(0xffffffffu, s, off);

    const float  e  = (s > 0.f) ? s : expm1f(s);   // elu, alpha=1
    const float4 v4 = make_float4(e, e, e, e);

    // warp owns float4 indices [warp*128, warp*128+128) of this 1024-f4 row
    float4* __restrict__ q =
        reinterpret_cast<float4*>(out) + (size_t)bo * (NN / 4) + warp * 128;
    q[lane]      = v4;
    q[lane + 32] = v4;
    q[lane + 64] = v4;
    q[lane + 96] = v4;
}

extern "C" void kernel_launch(void* const* d_in, const int* in_sizes, int n_in,
                              void* d_out, int out_size) {
    const float* x  = (const float*)d_in[0];   // [B, CIN, 1, NN]
    const float* W1 = (const float*)d_in[1];   // [OUT, CIN]
    // d_in[2] = w2, d_in[3] = bias_mat: unused (softmax over size-1 axis == 1)
    float* out = (float*)d_out;                // [B, OUT, 1, NN]

    k_rowsum<<<B * CIN, 256>>>(x);

    // Secondary launch with Programmatic Stream Serialization (PDL overlap).
    cudaLaunchConfig_t cfg = {};
    cfg.gridDim  = dim3(B * OUT, 1, 1);
    cfg.blockDim = dim3(256, 1, 1);
    cfg.dynamicSmemBytes = 0;
    cfg.stream = 0;
    cudaLaunchAttribute attr[1];
    attr[0].id = cudaLaunchAttributeProgrammaticStreamSerialization;
    attr[0].val.programmaticStreamSerializationAllowed = 1;
    cfg.attrs = attr;
    cfg.numAttrs = 1;
    cudaLaunchKernelEx(&cfg, k_out, W1, out);
}